// round 12
// baseline (speedup 1.0000x reference)
#include <cuda_runtime.h>
#include <math.h>

#define B_TOTAL 16384
#define T_LEN   512
#define NSTEP   511
#define HDIM    32
#define WID     64
#define BLK     256
#define GRID    256          /* 256 CTAs x 64 elements */

typedef unsigned long long u64;

// Tsit5 coefficients
__constant__ float cA[6][5] = {
    {0.f, 0.f, 0.f, 0.f, 0.f},
    {0.161f, 0.f, 0.f, 0.f, 0.f},
    {-0.008480655492356989f, 0.335480655492357f, 0.f, 0.f, 0.f},
    {2.8971530571054935f, -6.359448489975075f, 4.3622954328695815f, 0.f, 0.f},
    {5.325864828439257f, -11.748883564062828f, 7.4955393428898365f, -0.09249506636175525f, 0.f},
    {5.86145544294642f, -12.92096931784711f, 8.159367898576159f, -0.071584973281401f, -0.028269050394068383f}
};
__constant__ float cB[6] = {
    0.09646076681806523f, 0.01f, 0.4798896504144996f,
    1.379008574103742f, -3.290069515436081f, 2.324710524099774f
};

// Transposed, dt-scaled gradient increments, adjacent-pair layout:
// plane (n,c): float2[(n*3+c)*8192 + e/2] = (dq[e], dq[e+1])
__device__ float2 dqT2[(size_t)NSTEP * 3 * 8192];   // 100.5 MB scratch

// ---- packed f32x2 helpers ----
__device__ __forceinline__ u64 pack2(float lo, float hi) {
    u64 r; asm("mov.b64 %0, {%1, %2};" : "=l"(r) : "f"(lo), "f"(hi)); return r;
}
__device__ __forceinline__ void unpack2(u64 v, float& lo, float& hi) {
    asm("mov.b64 {%0, %1}, %2;" : "=f"(lo), "=f"(hi) : "l"(v));
}
__device__ __forceinline__ u64 dup2(float x) { return pack2(x, x); }
__device__ __forceinline__ u64 fma2(u64 a, u64 b, u64 c) {
    u64 d; asm("fma.rn.f32x2 %0, %1, %2, %3;" : "=l"(d) : "l"(a), "l"(b), "l"(c)); return d;
}

// SMEM layout (floats)
#define OFF_W1T 0                      /* [i=32][j=64] transposed : 2048 */
#define OFF_W2T (OFF_W1T + 2048)       /* [i=64][j=64]            : 4096 */
#define OFF_W3T (OFF_W2T + 4096)       /* [i=64][8 warps][16 pad] : 8192 */
#define OFF_B1  (OFF_W3T + 8192)       /* 64 */
#define OFF_B2  (OFF_B1 + 64)          /* 64 */
#define OFF_B3  (OFF_B2 + 64)          /* 96 */
#define OFF_Y   (OFF_B3 + 96)          /* u64 [32 comp][32 lane] : 2048 floats */
#define OFF_H1  (OFF_Y + 2048)         /* u64 [64][32] : 4096 */
#define OFF_H2  (OFF_H1 + 4096)        /* u64 [64][32] : 4096 */
#define SMEM_FLOATS (OFF_H2 + 4096)
#define SMEM_BYTES  (SMEM_FLOATS * 4)  /* 99,200 B -> 2 CTAs/SM (198 KB) */

// tanh(x) = 1 - 2/(e^{2x}+1); exact at 0 and +/-inf.
__device__ __forceinline__ float tanh_fast(float x) {
    float e = __expf(2.0f * x);
    float ep1 = e + 1.0f;
    float r; asm("rcp.approx.f32 %0, %1;" : "=f"(r) : "f"(ep1));
    return fmaf(-2.0f, r, 1.0f);
}

// ---- prep kernel: gradients (B,T,3) -> dqT planes, dt folded ----
__global__ void prep_dq(const float* __restrict__ grads,
                        const float* __restrict__ times)
{
    const int e = blockIdx.x * blockDim.x + threadIdx.x;   // 0..16383
    const int t = blockIdx.y;                              // 0..510
    const float dt = times[1] - times[0];
    const float* gp = grads + (size_t)e * T_LEN * 3 + t * 3;
    float v0 = gp[0] * dt;
    float v1 = gp[1] * dt;
    float v2 = gp[2] * dt;
    float* base = (float*)dqT2;
    base[((size_t)t * 3 + 0) * 16384 + e] = v0;
    base[((size_t)t * 3 + 1) * 16384 + e] = v1;
    base[((size_t)t * 3 + 2) * 16384 + e] = v2;
}

__global__ void __launch_bounds__(BLK, 2)
neural_cde_kernel(const float* __restrict__ w1g,
                  const float* __restrict__ b1g,
                  const float* __restrict__ w2g,
                  const float* __restrict__ b2g,
                  const float* __restrict__ w3g,
                  const float* __restrict__ b3g,
                  const float* __restrict__ wencg,
                  const float* __restrict__ bencg,
                  const float* __restrict__ wrog,
                  const float* __restrict__ brog,
                  float* __restrict__ out)
{
    extern __shared__ float sm[];
    float* w1t  = sm + OFF_W1T;
    float* w2t  = sm + OFF_W2T;
    float* w3t  = sm + OFF_W3T;
    float* b1s  = sm + OFF_B1;
    float* b2s  = sm + OFF_B2;
    float* b3s  = sm + OFF_B3;
    u64*   ysm  = (u64*)(sm + OFF_Y);
    u64*   h1sm = (u64*)(sm + OFF_H1);
    u64*   h2sm = (u64*)(sm + OFF_H2);

    const int tid  = threadIdx.x;
    const int w    = tid >> 5;     // warp = row-slice 0..7
    const int lane = tid & 31;     // lane = element pair within group

    // ---- stage weights (transposed) ----
    for (int idx = tid; idx < 2048; idx += BLK) {        // w1: [64][32] -> w1t[i][j]
        int j = idx >> 5, i = idx & 31;
        w1t[i * 64 + j] = w1g[idx];
    }
    for (int idx = tid; idx < 4096; idx += BLK) {        // w2: [64][64] -> w2t[i][j]
        int j = idx >> 6, i = idx & 63;
        w2t[i * 64 + j] = w2g[idx];
    }
    for (int idx = tid; idx < 6144; idx += BLK) {        // w3: [96][64] -> padded slices
        int r = idx >> 6, i = idx & 63;
        w3t[i * 128 + (r / 12) * 16 + (r % 12)] = w3g[idx];
    }
    for (int idx = tid; idx < 64; idx += BLK) b1s[idx] = b1g[idx];
    for (int idx = tid; idx < 64; idx += BLK) b2s[idx] = b2g[idx];
    for (int idx = tid; idx < 96; idx += BLK) b3s[idx] = b3g[idx];
    __syncthreads();

    const int g = blockIdx.x;
    const int pidx = g * 32 + lane;     // float2 index within each (n,c) plane

    // per-thread state: comps [4w, 4w+4), halves = (elemA=2*lane, elemB=2*lane+1)
    u64 zp[4], k0p[4], k1p[4], k2p[4], k3p[4], k4p[4], kvp[4];
#pragma unroll
    for (int p = 0; p < 4; p++) {
        int c = 4 * w + p;
        zp[p] = dup2(wencg[c] + bencg[c]);
        k0p[p] = k1p[p] = k2p[p] = k3p[p] = k4p[p] = 0ull;
    }

    const u64 bw0 = dup2(cB[0]), bw1 = dup2(cB[1]), bw2 = dup2(cB[2]);
    const u64 bw3 = dup2(cB[3]), bw4 = dup2(cB[4]), bw5 = dup2(cB[5]);

#pragma unroll 1
    for (int n = 0; n < NSTEP; n++) {
        // coalesced dq loads; consumed in phase 4 (hidden under phases 1-3)
        const float2 nd0 = dqT2[((size_t)n * 3 + 0) * 8192 + pidx];
        const float2 nd1 = dqT2[((size_t)n * 3 + 1) * 8192 + pidx];
        const float2 nd2 = dqT2[((size_t)n * 3 + 2) * 8192 + pidx];

#pragma unroll 1
        for (int s = 0; s < 6; s++) {
            const u64 a0 = dup2(cA[s][0]), a1 = dup2(cA[s][1]);
            const u64 a2 = dup2(cA[s][2]), a3 = dup2(cA[s][3]);
            const u64 a4 = dup2(cA[s][4]);

            // phase 1: y slice -> smem (zero coeffs are exact no-ops)
#pragma unroll
            for (int p = 0; p < 4; p++) {
                u64 acc = zp[p];
                acc = fma2(a0, k0p[p], acc);
                acc = fma2(a1, k1p[p], acc);
                acc = fma2(a2, k2p[p], acc);
                acc = fma2(a3, k3p[p], acc);
                acc = fma2(a4, k4p[p], acc);
                ysm[(4 * w + p) * 32 + lane] = acc;
            }
            __syncthreads();

            // phase 2: L1 rows [8w, 8w+8)
            {
                u64 accA[4], accB[4];
                const u64* bp = (const u64*)(b1s + 8 * w);
#pragma unroll
                for (int u = 0; u < 4; u++) { accA[u] = bp[u]; accB[u] = bp[u]; }
#pragma unroll 8
                for (int i = 0; i < HDIM; i++) {
                    float yA, yB;
                    unpack2(ysm[i * 32 + lane], yA, yB);
                    const u64 dA = dup2(yA), dB = dup2(yB);
                    const ulonglong2* wp = (const ulonglong2*)(w1t + i * 64 + 8 * w);
#pragma unroll
                    for (int q = 0; q < 2; q++) {
                        ulonglong2 wq = wp[q];
                        accA[2 * q + 0] = fma2(wq.x, dA, accA[2 * q + 0]);
                        accA[2 * q + 1] = fma2(wq.y, dA, accA[2 * q + 1]);
                        accB[2 * q + 0] = fma2(wq.x, dB, accB[2 * q + 0]);
                        accB[2 * q + 1] = fma2(wq.y, dB, accB[2 * q + 1]);
                    }
                }
#pragma unroll
                for (int u = 0; u < 4; u++) {
                    float aA0, aA1, aB0, aB1;
                    unpack2(accA[u], aA0, aA1);
                    unpack2(accB[u], aB0, aB1);
                    int r0 = 8 * w + 2 * u;
                    h1sm[r0 * 32 + lane]       = pack2(tanh_fast(aA0), tanh_fast(aB0));
                    h1sm[(r0 + 1) * 32 + lane] = pack2(tanh_fast(aA1), tanh_fast(aB1));
                }
            }
            __syncthreads();

            // phase 3: L2 rows [8w, 8w+8)
            {
                u64 accA[4], accB[4];
                const u64* bp = (const u64*)(b2s + 8 * w);
#pragma unroll
                for (int u = 0; u < 4; u++) { accA[u] = bp[u]; accB[u] = bp[u]; }
#pragma unroll 8
                for (int i = 0; i < WID; i++) {
                    float hA, hB;
                    unpack2(h1sm[i * 32 + lane], hA, hB);
                    const u64 dA = dup2(hA), dB = dup2(hB);
                    const ulonglong2* wp = (const ulonglong2*)(w2t + i * 64 + 8 * w);
#pragma unroll
                    for (int q = 0; q < 2; q++) {
                        ulonglong2 wq = wp[q];
                        accA[2 * q + 0] = fma2(wq.x, dA, accA[2 * q + 0]);
                        accA[2 * q + 1] = fma2(wq.y, dA, accA[2 * q + 1]);
                        accB[2 * q + 0] = fma2(wq.x, dB, accB[2 * q + 0]);
                        accB[2 * q + 1] = fma2(wq.y, dB, accB[2 * q + 1]);
                    }
                }
#pragma unroll
                for (int u = 0; u < 4; u++) {
                    float aA0, aA1, aB0, aB1;
                    unpack2(accA[u], aA0, aA1);
                    unpack2(accB[u], aB0, aB1);
                    int r0 = 8 * w + 2 * u;
                    h2sm[r0 * 32 + lane]       = pack2(tanh_fast(aA0), tanh_fast(aB0));
                    h2sm[(r0 + 1) * 32 + lane] = pack2(tanh_fast(aA1), tanh_fast(aB1));
                }
            }
            __syncthreads();

            // phase 4: L3 rows [12w, 12w+12) + dq contraction
            {
                u64 accA[6], accB[6];
                const u64* bp = (const u64*)(b3s + 12 * w);   // 48w bytes, 8B-aligned
#pragma unroll
                for (int u = 0; u < 6; u++) { accA[u] = bp[u]; accB[u] = bp[u]; }
#pragma unroll 8
                for (int i = 0; i < WID; i++) {
                    float hA, hB;
                    unpack2(h2sm[i * 32 + lane], hA, hB);
                    const u64 dA = dup2(hA), dB = dup2(hB);
                    // padded slice: 16 floats per warp -> 64B, 16B-aligned
                    const ulonglong2* wp = (const ulonglong2*)(w3t + i * 128 + 16 * w);
#pragma unroll
                    for (int q = 0; q < 3; q++) {
                        ulonglong2 wq = wp[q];
                        accA[2 * q + 0] = fma2(wq.x, dA, accA[2 * q + 0]);
                        accA[2 * q + 1] = fma2(wq.y, dA, accA[2 * q + 1]);
                        accB[2 * q + 0] = fma2(wq.x, dB, accB[2 * q + 0]);
                        accB[2 * q + 1] = fma2(wq.y, dB, accB[2 * q + 1]);
                    }
                }
                float fA[12], fB[12];
#pragma unroll
                for (int u = 0; u < 6; u++) {
                    unpack2(accA[u], fA[2 * u], fA[2 * u + 1]);
                    unpack2(accB[u], fB[2 * u], fB[2 * u + 1]);
                }
#pragma unroll
                for (int p = 0; p < 4; p++) {
                    float kA = fA[3 * p] * nd0.x;
                    kA = fmaf(fA[3 * p + 1], nd1.x, kA);
                    kA = fmaf(fA[3 * p + 2], nd2.x, kA);
                    float kB = fB[3 * p] * nd0.y;
                    kB = fmaf(fB[3 * p + 1], nd1.y, kB);
                    kB = fmaf(fB[3 * p + 2], nd2.y, kB);
                    kvp[p] = pack2(kA, kB);
                }
            }

            if (s == 0) {
#pragma unroll
                for (int p = 0; p < 4; p++) k0p[p] = kvp[p];
            } else if (s == 1) {
#pragma unroll
                for (int p = 0; p < 4; p++) k1p[p] = kvp[p];
            } else if (s == 2) {
#pragma unroll
                for (int p = 0; p < 4; p++) k2p[p] = kvp[p];
            } else if (s == 3) {
#pragma unroll
                for (int p = 0; p < 4; p++) k3p[p] = kvp[p];
            } else if (s == 4) {
#pragma unroll
                for (int p = 0; p < 4; p++) k4p[p] = kvp[p];
            }
        } // stages

#pragma unroll
        for (int p = 0; p < 4; p++) {
            u64 acc = fma2(bw5, kvp[p], zp[p]);
            acc = fma2(bw0, k0p[p], acc);
            acc = fma2(bw1, k1p[p], acc);
            acc = fma2(bw2, k2p[p], acc);
            acc = fma2(bw3, k3p[p], acc);
            acc = fma2(bw4, k4p[p], acc);
            zp[p] = acc;
        }
    } // steps

    // readout: 8 per-warp partial dots, reduce via smem; coalesced float2 out
    {
        float partA = 0.0f, partB = 0.0f;
#pragma unroll
        for (int p = 0; p < 4; p++) {
            float zA, zB;
            unpack2(zp[p], zA, zB);
            float wr = wrog[4 * w + p];
            partA = fmaf(zA, wr, partA);
            partB = fmaf(zB, wr, partB);
        }
        float* red = (float*)ysm;  // 512 floats scratch
        red[w * 32 + lane]        = partA;
        red[256 + w * 32 + lane]  = partB;
        __syncthreads();
        if (tid < 32) {
            int l = tid;
            float b0 = brog[0];
            float logitA = 0.0f, logitB = 0.0f;
#pragma unroll
            for (int q = 0; q < 8; q++) {
                logitA += red[q * 32 + l];
                logitB += red[256 + q * 32 + l];
            }
            logitA += b0;
            logitB += b0;
            float sA = __fdividef(1.0f, 1.0f + __expf(-logitA));
            float sB = __fdividef(1.0f, 1.0f + __expf(-logitB));
            ((float2*)out)[g * 32 + l] = make_float2(sA, sB);
        }
    }
}

extern "C" void kernel_launch(void* const* d_in, const int* in_sizes, int n_in,
                              void* d_out, int out_size)
{
    const float* times = (const float*)d_in[0];
    const float* grads = (const float*)d_in[1];
    const float* w1    = (const float*)d_in[2];
    const float* b1    = (const float*)d_in[3];
    const float* w2    = (const float*)d_in[4];
    const float* b2    = (const float*)d_in[5];
    const float* w3    = (const float*)d_in[6];
    const float* b3    = (const float*)d_in[7];
    const float* wenc  = (const float*)d_in[8];
    const float* benc  = (const float*)d_in[9];
    const float* wro   = (const float*)d_in[10];
    const float* bro   = (const float*)d_in[11];
    float* out = (float*)d_out;

    // 1) transpose + dt-fold gradients into coalesced planes
    dim3 pgrid(B_TOTAL / 256, NSTEP);
    prep_dq<<<pgrid, 256>>>(grads, times);

    // 2) main kernel: 8-warp row-split, 16 warps/SM
    cudaFuncSetAttribute(neural_cde_kernel,
                         cudaFuncAttributeMaxDynamicSharedMemorySize, SMEM_BYTES);
    neural_cde_kernel<<<GRID, BLK, SMEM_BYTES>>>(
        w1, b1, w2, b2, w3, b3, wenc, benc, wro, bro, out);
}

// round 15
// speedup vs baseline: 2.8415x; 2.8415x over previous
#include <cuda_runtime.h>
#include <cuda_bf16.h>
#include <cstdint>

#define T_LEN 512
#define NSTEP 511
#define BLK   256
#define GRID  128

__constant__ float cAc[6][5] = {
    {0.f,0.f,0.f,0.f,0.f},
    {0.161f,0.f,0.f,0.f,0.f},
    {-0.008480655492356989f,0.335480655492357f,0.f,0.f,0.f},
    {2.8971530571054935f,-6.359448489975075f,4.3622954328695815f,0.f,0.f},
    {5.325864828439257f,-11.748883564062828f,7.4955393428898365f,-0.09249506636175525f,0.f},
    {5.86145544294642f,-12.92096931784711f,8.159367898576159f,-0.071584973281401f,-0.028269050394068383f}
};
__constant__ float cBc[6] = {
    0.09646076681806523f,0.01f,0.4798896504144996f,
    1.379008574103742f,-3.290069515436081f,2.324710524099774f
};

// dt-folded transposed gradient planes: dqT[(n*3+c)*16384 + e]
__device__ float dqT[(size_t)NSTEP * 3 * 16384];
// pre-packed per-lane B fragments (192 tiles x 32 lanes x uint2)
__device__ uint2 gWpack[192 * 32];

// tile bases in gWpack
#define G1_HI 0     /* 16: n(0..7)*2 + k(0..1) */
#define G1_LO 16
#define G2_HI 32    /* 32: n(0..7)*4 + k(0..3) */
#define G2_LO 64
#define G3_HI 96    /* 48: (c(0..2)*4 + n(0..3))*4 + k(0..3) */
#define G3_LO 144

// SMEM: Wsm 49152 B + biases 896 B
#define SM_BIAS   49152
#define SMEM_BYTES (SM_BIAS + 224 * 4)

__device__ __forceinline__ uint32_t pack_bf16x2(float lo_f, float hi_f) {
    uint32_t r;
    asm("cvt.rn.bf16x2.f32 %0, %1, %2;" : "=r"(r) : "f"(hi_f), "f"(lo_f));
    return r;
}
// split (v0,v1) -> hi pair + residual-lo pair (bf16x2 each, low half = v0)
__device__ __forceinline__ void split2(float v0, float v1, uint32_t& hi, uint32_t& lo) {
    asm("cvt.rn.bf16x2.f32 %0, %1, %2;" : "=r"(hi) : "f"(v1), "f"(v0));
    float h0 = __uint_as_float(hi << 16);
    float h1 = __uint_as_float(hi & 0xFFFF0000u);
    asm("cvt.rn.bf16x2.f32 %0, %1, %2;" : "=r"(lo) : "f"(v1 - h1), "f"(v0 - h0));
}
__device__ __forceinline__ void mma16816(float* c, const uint32_t* a, uint2 b) {
    asm volatile(
        "mma.sync.aligned.m16n8k16.row.col.f32.bf16.bf16.f32 "
        "{%0,%1,%2,%3}, {%4,%5,%6,%7}, {%8,%9}, {%0,%1,%2,%3};"
        : "+f"(c[0]), "+f"(c[1]), "+f"(c[2]), "+f"(c[3])
        : "r"(a[0]), "r"(a[1]), "r"(a[2]), "r"(a[3]), "r"(b.x), "r"(b.y));
}
__device__ __forceinline__ float tanh_fast(float x) {
    float e = __expf(2.0f * x);
    float r; asm("rcp.approx.f32 %0, %1;" : "=f"(r) : "f"(e + 1.0f));
    return fmaf(-2.0f, r, 1.0f);
}

// ---- prep: dq planes ----
__global__ void prep_dq(const float* __restrict__ grads, const float* __restrict__ times) {
    const int e = blockIdx.x * blockDim.x + threadIdx.x;
    const int t = blockIdx.y;
    const float dt = times[1] - times[0];
    const float* gp = grads + (size_t)e * T_LEN * 3 + t * 3;
    dqT[((size_t)t * 3 + 0) * 16384 + e] = gp[0] * dt;
    dqT[((size_t)t * 3 + 1) * 16384 + e] = gp[1] * dt;
    dqT[((size_t)t * 3 + 2) * 16384 + e] = gp[2] * dt;
}

// ---- prep: pack weights into per-lane mma B fragments (hi/lo split) ----
__global__ void prep_wpack(const float* __restrict__ w1,
                           const float* __restrict__ w2,
                           const float* __restrict__ w3)
{
    int t = blockIdx.x * blockDim.x + threadIdx.x;
    if (t >= 192 * 32) return;
    int tile = t >> 5, lane = t & 31;
    int gdx = lane >> 2, tig = lane & 3;
    int kk = 2 * tig;
    float v[4];
    bool lo;
    if (tile < 32) {                        // GEMM1: W1 [64][32]
        lo = tile >= 16; int tt = tile & 15;
        int nt = tt >> 1, kt = tt & 1;
        int r = nt * 8 + gdx, k0 = kt * 16 + kk;
        v[0] = w1[r * 32 + k0];     v[1] = w1[r * 32 + k0 + 1];
        v[2] = w1[r * 32 + k0 + 8]; v[3] = w1[r * 32 + k0 + 9];
    } else if (tile < 96) {                 // GEMM2: W2 [64][64]
        int tt = tile - 32; lo = tt >= 32; tt &= 31;
        int nt = tt >> 2, kt = tt & 3;
        int r = nt * 8 + gdx, k0 = kt * 16 + kk;
        v[0] = w2[r * 64 + k0];     v[1] = w2[r * 64 + k0 + 1];
        v[2] = w2[r * 64 + k0 + 8]; v[3] = w2[r * 64 + k0 + 9];
    } else {                                // GEMM3: W3_c[h][k] = w3[(3h+c)*64+k]
        int tt = tile - 96; lo = tt >= 48; tt %= 48;
        int c = tt >> 4, nt = (tt >> 2) & 3, kt = tt & 3;
        int h = nt * 8 + gdx, r = 3 * h + c, k0 = kt * 16 + kk;
        v[0] = w3[r * 64 + k0];     v[1] = w3[r * 64 + k0 + 1];
        v[2] = w3[r * 64 + k0 + 8]; v[3] = w3[r * 64 + k0 + 9];
    }
    if (lo) {
#pragma unroll
        for (int i = 0; i < 4; i++) {
            __nv_bfloat16 h = __float2bfloat16(v[i]);
            v[i] = v[i] - __bfloat162float(h);
        }
    }
    gWpack[t] = make_uint2(pack_bf16x2(v[0], v[1]), pack_bf16x2(v[2], v[3]));
}

__global__ void __launch_bounds__(BLK, 1)
neural_cde_mma(const float* __restrict__ b1g,
               const float* __restrict__ b2g,
               const float* __restrict__ b3g,
               const float* __restrict__ wencg,
               const float* __restrict__ bencg,
               const float* __restrict__ wrog,
               const float* __restrict__ brog,
               float* __restrict__ out)
{
    extern __shared__ char smem[];
    uint2* Wsm = (uint2*)smem;
    float* b1s = (float*)(smem + SM_BIAS);
    float* b2s = b1s + 64;
    float* b3s = b2s + 64;

    const int tid  = threadIdx.x;
    const int wid  = tid >> 5;
    const int lane = tid & 31;
    const int g    = lane >> 2;
    const int q    = lane & 3;

    for (int i = tid; i < 192 * 32; i += BLK) Wsm[i] = gWpack[i];
    for (int i = tid; i < 64; i += BLK) b1s[i] = b1g[i];
    for (int i = tid; i < 64; i += BLK) b2s[i] = b2g[i];
    for (int i = tid; i < 96; i += BLK) b3s[i] = b3g[i];
    __syncthreads();

    // state fragments: j = tn*4+cc -> (row = g + 8*(cc>>1), col = 8*tn + 2q + (cc&1))
    float z[16], k1[16], k2[16], k3[16], k4[16], k5[16], kv[16];
#pragma unroll
    for (int j = 0; j < 16; j++) {
        int col = 8 * (j >> 2) + 2 * q + (j & 1);
        z[j] = wencg[col] + bencg[col];
        k1[j] = k2[j] = k3[j] = k4[j] = k5[j] = 0.0f;
    }

    const int row0 = blockIdx.x * 128 + wid * 16 + g;   // element of rows g
    const int row1 = row0 + 8;                          // element of rows g+8

#pragma unroll 1
    for (int n = 0; n < NSTEP; n++) {
        float dqa[3], dqb[3];
#pragma unroll
        for (int c = 0; c < 3; c++) {
            dqa[c] = dqT[((size_t)n * 3 + c) * 16384 + row0];
            dqb[c] = dqT[((size_t)n * 3 + c) * 16384 + row1];
        }

#pragma unroll 1
        for (int s = 0; s < 6; s++) {
            // ---- y = z + sum A*k; split into A-frags (2 k-tiles) ----
            uint32_t yh[2][4], yl[2][4];
            {
                const float a0 = cAc[s][0], a1 = cAc[s][1], a2 = cAc[s][2];
                const float a3 = cAc[s][3], a4 = cAc[s][4];
                float y[16];
#pragma unroll
                for (int j = 0; j < 16; j++) {
                    float acc = z[j];
                    acc = fmaf(a0, k1[j], acc); acc = fmaf(a1, k2[j], acc);
                    acc = fmaf(a2, k3[j], acc); acc = fmaf(a3, k4[j], acc);
                    acc = fmaf(a4, k5[j], acc);
                    y[j] = acc;
                }
#pragma unroll
                for (int i = 0; i < 8; i++)
                    split2(y[2 * i], y[2 * i + 1], yh[i >> 2][i & 3], yl[i >> 2][i & 3]);
            }

            // ---- GEMM1: C[16x64] = y * W1^T  (K=32) ----
            float C[32];
#pragma unroll
            for (int j = 0; j < 32; j++) C[j] = 0.0f;
#pragma unroll
            for (int k = 0; k < 2; k++) {
#pragma unroll
                for (int nt = 0; nt < 8; nt++) {
                    uint2 bh = Wsm[(G1_HI + nt * 2 + k) * 32 + lane];
                    mma16816(C + 4 * nt, yh[k], bh);
                    mma16816(C + 4 * nt, yl[k], bh);
                    uint2 bl = Wsm[(G1_LO + nt * 2 + k) * 32 + lane];
                    mma16816(C + 4 * nt, yh[k], bl);
                }
            }

            // ---- epi1: h1 = tanh(C + b1) -> A-frags (4 k-tiles) ----
            uint32_t ah[4][4], al[4][4];
#pragma unroll
            for (int i = 0; i < 16; i++) {
                float2 bias = *(float2*)(b1s + 8 * (i >> 1) + 2 * q);
                float t0 = tanh_fast(C[2 * i] + bias.x);
                float t1 = tanh_fast(C[2 * i + 1] + bias.y);
                split2(t0, t1, ah[i >> 2][i & 3], al[i >> 2][i & 3]);
            }

            // ---- GEMM2: C = h1 * W2^T  (K=64) ----
#pragma unroll
            for (int j = 0; j < 32; j++) C[j] = 0.0f;
#pragma unroll
            for (int k = 0; k < 4; k++) {
#pragma unroll
                for (int nt = 0; nt < 8; nt++) {
                    uint2 bh = Wsm[(G2_HI + nt * 4 + k) * 32 + lane];
                    mma16816(C + 4 * nt, ah[k], bh);
                    mma16816(C + 4 * nt, al[k], bh);
                    uint2 bl = Wsm[(G2_LO + nt * 4 + k) * 32 + lane];
                    mma16816(C + 4 * nt, ah[k], bl);
                }
            }

            // ---- epi2: h2 = tanh(C + b2) -> A-frags ----
#pragma unroll
            for (int i = 0; i < 16; i++) {
                float2 bias = *(float2*)(b2s + 8 * (i >> 1) + 2 * q);
                float t0 = tanh_fast(C[2 * i] + bias.x);
                float t1 = tanh_fast(C[2 * i + 1] + bias.y);
                split2(t0, t1, ah[i >> 2][i & 3], al[i >> 2][i & 3]);
            }

            // ---- GEMM3 per channel + dq contraction ----
#pragma unroll
            for (int j = 0; j < 16; j++) kv[j] = 0.0f;
#pragma unroll
            for (int c = 0; c < 3; c++) {
                float C3[16];
#pragma unroll
                for (int j = 0; j < 16; j++) C3[j] = 0.0f;
#pragma unroll
                for (int k = 0; k < 4; k++) {
#pragma unroll
                    for (int nt = 0; nt < 4; nt++) {
                        int t3 = (c * 4 + nt) * 4 + k;
                        uint2 bh = Wsm[(G3_HI + t3) * 32 + lane];
                        mma16816(C3 + 4 * nt, ah[k], bh);
                        mma16816(C3 + 4 * nt, al[k], bh);
                        uint2 bl = Wsm[(G3_LO + t3) * 32 + lane];
                        mma16816(C3 + 4 * nt, ah[k], bl);
                    }
                }
                float dq_r0 = dqa[c], dq_r1 = dqb[c];
#pragma unroll
                for (int j = 0; j < 16; j++) {
                    int col = 8 * (j >> 2) + 2 * q + (j & 1);
                    float f = C3[j] + b3s[3 * col + c];
                    kv[j] = fmaf(f, (j & 2) ? dq_r1 : dq_r0, kv[j]);
                }
            }

            if (s == 0) {
#pragma unroll
                for (int j = 0; j < 16; j++) k1[j] = kv[j];
            } else if (s == 1) {
#pragma unroll
                for (int j = 0; j < 16; j++) k2[j] = kv[j];
            } else if (s == 2) {
#pragma unroll
                for (int j = 0; j < 16; j++) k3[j] = kv[j];
            } else if (s == 3) {
#pragma unroll
                for (int j = 0; j < 16; j++) k4[j] = kv[j];
            } else if (s == 4) {
#pragma unroll
                for (int j = 0; j < 16; j++) k5[j] = kv[j];
            }
        } // stages

#pragma unroll
        for (int j = 0; j < 16; j++) {
            float acc = fmaf(cBc[5], kv[j], z[j]);
            acc = fmaf(cBc[0], k1[j], acc);
            acc = fmaf(cBc[1], k2[j], acc);
            acc = fmaf(cBc[2], k3[j], acc);
            acc = fmaf(cBc[3], k4[j], acc);
            acc = fmaf(cBc[4], k5[j], acc);
            z[j] = acc;
        }
    } // steps

    // ---- readout: per-row dot over quad, sigmoid ----
    {
        float pr0 = 0.0f, pr1 = 0.0f;
#pragma unroll
        for (int j = 0; j < 16; j++) {
            int col = 8 * (j >> 2) + 2 * q + (j & 1);
            float wr = wrog[col];
            if (j & 2) pr1 = fmaf(z[j], wr, pr1);
            else       pr0 = fmaf(z[j], wr, pr0);
        }
        pr0 += __shfl_xor_sync(0xFFFFFFFFu, pr0, 1);
        pr0 += __shfl_xor_sync(0xFFFFFFFFu, pr0, 2);
        pr1 += __shfl_xor_sync(0xFFFFFFFFu, pr1, 1);
        pr1 += __shfl_xor_sync(0xFFFFFFFFu, pr1, 2);
        if (q == 0) {
            float b0 = brog[0];
            out[row0] = __fdividef(1.0f, 1.0f + __expf(-(pr0 + b0)));
            out[row1] = __fdividef(1.0f, 1.0f + __expf(-(pr1 + b0)));
        }
    }
}

extern "C" void kernel_launch(void* const* d_in, const int* in_sizes, int n_in,
                              void* d_out, int out_size)
{
    const float* times = (const float*)d_in[0];
    const float* grads = (const float*)d_in[1];
    const float* w1    = (const float*)d_in[2];
    const float* b1    = (const float*)d_in[3];
    const float* w2    = (const float*)d_in[4];
    const float* b2    = (const float*)d_in[5];
    const float* w3    = (const float*)d_in[6];
    const float* b3    = (const float*)d_in[7];
    const float* wenc  = (const float*)d_in[8];
    const float* benc  = (const float*)d_in[9];
    const float* wro   = (const float*)d_in[10];
    const float* bro   = (const float*)d_in[11];
    float* out = (float*)d_out;

    dim3 pgrid(16384 / 256, NSTEP);
    prep_dq<<<pgrid, 256>>>(grads, times);
    prep_wpack<<<24, 256>>>(w1, w2, w3);

    cudaFuncSetAttribute(neural_cde_mma,
                         cudaFuncAttributeMaxDynamicSharedMemorySize, SMEM_BYTES);
    neural_cde_mma<<<GRID, BLK, SMEM_BYTES>>>(
        b1, b2, b3, wenc, benc, wro, bro, out);
}